// round 3
// baseline (speedup 1.0000x reference)
#include <cuda_runtime.h>
#include <cuda_bf16.h>
#include <stdint.h>

#define NN  50000
#define EE  800000

// ---------------- scratch (device globals: no allocation allowed) ----------
__device__ __align__(16) float g_t[NN * 128];   // t = h @ w_l
__device__ __align__(16) float g_r[NN * 128];   // r = h @ w_r
__device__ __align__(16) float g_h[NN * 128];   // layer activations
__device__ int   g_degc[NN];
__device__ int   g_rowoff[NN + 1];
__device__ int   g_wptr[NN];
__device__ int   g_csr[EE];
__device__ float g_invdeg[NN];
__device__ int   g_is64;   // 1 if edge_index is int64, 0 if int32

// ---------------- dtype detection ------------------------------------------
// Reads the first 1024 entries as int64. int64 data -> all in [0, NN).
// int32 data read as int64 fuses adjacent pairs -> huge values -> detected.
// (1024 int64 reads = 8 KB, within even the int32 buffer's 6.4 MB.)
__global__ void detect_kernel(const long long* __restrict__ ei) {
    __shared__ int ok;
    if (threadIdx.x == 0) ok = 1;
    __syncthreads();
    for (int i = threadIdx.x; i < 1024; i += blockDim.x) {
        long long v = ei[i];
        if (v < 0 || v >= NN) ok = 0;
    }
    __syncthreads();
    if (threadIdx.x == 0) g_is64 = ok;
}

__device__ __forceinline__ void load_edge(const void* ei, int e, int is64,
                                          int& s, int& d) {
    if (is64) {
        const long long* p = (const long long*)ei;
        s = (int)p[e];
        d = (int)p[EE + e];
    } else {
        const int* p = (const int*)ei;
        s = p[e];
        d = p[EE + e];
    }
    // defensive clamp: no input data may ever produce an OOB address
    s = min(max(s, 0), NN - 1);
    d = min(max(d, 0), NN - 1);
}

// ---------------- graph preprocessing --------------------------------------
__global__ void zero_degc_kernel() {
    int i = blockIdx.x * blockDim.x + threadIdx.x;
    if (i < NN) g_degc[i] = 0;
}

__global__ void count_deg_kernel(const void* __restrict__ ei) {
    int e = blockIdx.x * blockDim.x + threadIdx.x;
    if (e < EE) {
        int s, d;
        load_edge(ei, e, g_is64, s, d);
        atomicAdd(&g_degc[d], 1);
    }
}

// single-block exclusive scan over N=50000 degree counts
__global__ void scan_kernel() {
    __shared__ int part[1024];
    const int tid = threadIdx.x;
    const int CH = (NN + 1023) / 1024;           // 49
    int start = tid * CH;
    int end   = start + CH; if (end > NN) end = NN;
    if (start > NN) start = NN;

    int s = 0;
    for (int i = start; i < end; i++) s += g_degc[i];
    part[tid] = s;
    __syncthreads();
    for (int off = 1; off < 1024; off <<= 1) {
        int v = (tid >= off) ? part[tid - off] : 0;
        __syncthreads();
        part[tid] += v;
        __syncthreads();
    }
    int run = (tid == 0) ? 0 : part[tid - 1];
    for (int i = start; i < end; i++) {
        g_rowoff[i] = run;
        g_wptr[i]   = run;
        int d = g_degc[i];
        g_invdeg[i] = 1.0f / fmaxf((float)d, 1.0f);
        run += d;
    }
    if (tid == 1023) g_rowoff[NN] = part[1023];
}

__global__ void fill_csr_kernel(const void* __restrict__ ei) {
    int e = blockIdx.x * blockDim.x + threadIdx.x;
    if (e < EE) {
        int s, d;
        load_edge(ei, e, g_is64, s, d);
        int p = atomicAdd(&g_wptr[d], 1);
        if (p >= 0 && p < EE) g_csr[p] = s;
    }
}

// ---------------- dual GEMM: t = A @ Wl, r = A @ Wr ------------------------
// block tile: 64 rows x 64 cols, 256 threads, 4x4 microtile per thread.
// K=128 processed in two 64-wide chunks; static smem = 33 KB.
#define ASTRIDE 66
#define KCH 64

template <int DINp, int DOUTp>
__global__ __launch_bounds__(256)
void gemm_dual_kernel(const float* __restrict__ A,
                      const float* __restrict__ Wl,
                      const float* __restrict__ Wr) {
    __shared__ float As[KCH * ASTRIDE];   // 16.5 KB
    __shared__ float Ws[KCH * 64];        // 16   KB

    const float* Ap = A ? A : g_h;

    const int tid = threadIdx.x;
    const int tx = tid & 15;
    const int ty = tid >> 4;
    const int rowBase = blockIdx.x * 64;
    const int cb = blockIdx.y;
    const bool isL = cb < (DOUTp / 64);
    const float* W = isL ? Wl : Wr;
    const int colBase = (isL ? cb : cb - (DOUTp / 64)) * 64;
    float* Cout = isL ? g_t : g_r;

    float acc[4][4];
#pragma unroll
    for (int i = 0; i < 4; i++)
#pragma unroll
        for (int j = 0; j < 4; j++) acc[i][j] = 0.f;

    for (int kc = 0; kc < DINp; kc += KCH) {
        // stage A chunk (transposed): 64 rows x 64 k
        {
            int row = tid >> 2;            // 0..63
            int kq  = tid & 3;             // 0..3
            int grow = rowBase + row;
#pragma unroll
            for (int p = 0; p < 4; p++) {
                int kk = kq * 4 + p * 16;
                float4 v = make_float4(0.f, 0.f, 0.f, 0.f);
                if (grow < NN)
                    v = *(const float4*)(Ap + (size_t)grow * DINp + kc + kk);
                As[(kk + 0) * ASTRIDE + row] = v.x;
                As[(kk + 1) * ASTRIDE + row] = v.y;
                As[(kk + 2) * ASTRIDE + row] = v.z;
                As[(kk + 3) * ASTRIDE + row] = v.w;
            }
        }
        // stage W chunk: 64 k x 64 cols
        for (int f = tid; f < KCH * 16; f += 256) {
            int k = f >> 4, c = f & 15;
            float4 v = *(const float4*)(W + (size_t)(kc + k) * DOUTp + colBase + c * 4);
            *(float4*)(Ws + k * 64 + c * 4) = v;
        }
        __syncthreads();

#pragma unroll 8
        for (int k = 0; k < KCH; k++) {
            const float* ap = As + k * ASTRIDE + (ty << 2);
            float2 a0 = *(const float2*)(ap);
            float2 a1 = *(const float2*)(ap + 2);
            float4 b  = *(const float4*)(Ws + (k << 6) + (tx << 2));
            acc[0][0] += a0.x * b.x; acc[0][1] += a0.x * b.y;
            acc[0][2] += a0.x * b.z; acc[0][3] += a0.x * b.w;
            acc[1][0] += a0.y * b.x; acc[1][1] += a0.y * b.y;
            acc[1][2] += a0.y * b.z; acc[1][3] += a0.y * b.w;
            acc[2][0] += a1.x * b.x; acc[2][1] += a1.x * b.y;
            acc[2][2] += a1.x * b.z; acc[2][3] += a1.x * b.w;
            acc[3][0] += a1.y * b.x; acc[3][1] += a1.y * b.y;
            acc[3][2] += a1.y * b.z; acc[3][3] += a1.y * b.w;
        }
        __syncthreads();
    }

#pragma unroll
    for (int i = 0; i < 4; i++) {
        int grow = rowBase + (ty << 2) + i;
        if (grow < NN) {
            float4 o = make_float4(acc[i][0], acc[i][1], acc[i][2], acc[i][3]);
            *(float4*)(Cout + (size_t)grow * DOUTp + colBase + (tx << 2)) = o;
        }
    }
}

// ---------------- aggregation + combine: out = relu?(mean(t[src]) + b + r) -
// one warp per dst node, each lane owns D/32 contiguous floats.
template <int D, bool RELU>
__global__ __launch_bounds__(256)
void combine_kernel(const float* __restrict__ bias, float* __restrict__ outp) {
    int gw = (blockIdx.x * blockDim.x + threadIdx.x) >> 5;
    int lane = threadIdx.x & 31;
    if (gw >= NN) return;
    float* out = outp ? outp : g_h;

    int beg = g_rowoff[gw];
    int end = g_rowoff[gw + 1];

    if (D == 128) {
        float4 acc = make_float4(0.f, 0.f, 0.f, 0.f);
        const float* t = g_t;
        int j = beg;
        for (; j + 4 <= end; j += 4) {
            int s0 = g_csr[j], s1 = g_csr[j + 1], s2 = g_csr[j + 2], s3 = g_csr[j + 3];
            float4 v0 = *(const float4*)(t + (size_t)s0 * 128 + lane * 4);
            float4 v1 = *(const float4*)(t + (size_t)s1 * 128 + lane * 4);
            float4 v2 = *(const float4*)(t + (size_t)s2 * 128 + lane * 4);
            float4 v3 = *(const float4*)(t + (size_t)s3 * 128 + lane * 4);
            acc.x += v0.x + v1.x + v2.x + v3.x;
            acc.y += v0.y + v1.y + v2.y + v3.y;
            acc.z += v0.z + v1.z + v2.z + v3.z;
            acc.w += v0.w + v1.w + v2.w + v3.w;
        }
        for (; j < end; j++) {
            int s = g_csr[j];
            float4 v = *(const float4*)(t + (size_t)s * 128 + lane * 4);
            acc.x += v.x; acc.y += v.y; acc.z += v.z; acc.w += v.w;
        }
        float inv = g_invdeg[gw];
        float4 rr = *(const float4*)(g_r + (size_t)gw * 128 + lane * 4);
        float4 o;
        o.x = acc.x * inv + bias[lane * 4 + 0] + rr.x;
        o.y = acc.y * inv + bias[lane * 4 + 1] + rr.y;
        o.z = acc.z * inv + bias[lane * 4 + 2] + rr.z;
        o.w = acc.w * inv + bias[lane * 4 + 3] + rr.w;
        if (RELU) {
            o.x = fmaxf(o.x, 0.f); o.y = fmaxf(o.y, 0.f);
            o.z = fmaxf(o.z, 0.f); o.w = fmaxf(o.w, 0.f);
        }
        *(float4*)(out + (size_t)gw * 128 + lane * 4) = o;
    } else {  // D == 64
        float2 acc = make_float2(0.f, 0.f);
        const float* t = g_t;
        int j = beg;
        for (; j + 4 <= end; j += 4) {
            int s0 = g_csr[j], s1 = g_csr[j + 1], s2 = g_csr[j + 2], s3 = g_csr[j + 3];
            float2 v0 = *(const float2*)(t + (size_t)s0 * 64 + lane * 2);
            float2 v1 = *(const float2*)(t + (size_t)s1 * 64 + lane * 2);
            float2 v2 = *(const float2*)(t + (size_t)s2 * 64 + lane * 2);
            float2 v3 = *(const float2*)(t + (size_t)s3 * 64 + lane * 2);
            acc.x += v0.x + v1.x + v2.x + v3.x;
            acc.y += v0.y + v1.y + v2.y + v3.y;
        }
        for (; j < end; j++) {
            int s = g_csr[j];
            float2 v = *(const float2*)(t + (size_t)s * 64 + lane * 2);
            acc.x += v.x; acc.y += v.y;
        }
        float inv = g_invdeg[gw];
        float2 rr = *(const float2*)(g_r + (size_t)gw * 64 + lane * 2);
        float2 o;
        o.x = acc.x * inv + bias[lane * 2 + 0] + rr.x;
        o.y = acc.y * inv + bias[lane * 2 + 1] + rr.y;
        if (RELU) { o.x = fmaxf(o.x, 0.f); o.y = fmaxf(o.y, 0.f); }
        *(float2*)(out + (size_t)gw * 64 + lane * 2) = o;
    }
}

// ---------------- launch ----------------------------------------------------
extern "C" void kernel_launch(void* const* d_in, const int* in_sizes, int n_in,
                              void* d_out, int out_size) {
    const float* x    = (const float*)d_in[0];
    const void*  ei   = d_in[1];                 // int32 or int64, detected on device
    const float* w_l0 = (const float*)d_in[2];
    const float* b0   = (const float*)d_in[3];
    const float* w_r0 = (const float*)d_in[4];
    const float* w_l1 = (const float*)d_in[5];
    const float* b1   = (const float*)d_in[6];
    const float* w_r1 = (const float*)d_in[7];
    const float* w_l2 = (const float*)d_in[8];
    const float* b2   = (const float*)d_in[9];
    const float* w_r2 = (const float*)d_in[10];
    float* outp = (float*)d_out;

    // graph preprocessing (recomputed every launch; deterministic)
    detect_kernel<<<1, 256>>>((const long long*)ei);
    zero_degc_kernel<<<(NN + 255) / 256, 256>>>();
    count_deg_kernel<<<(EE + 255) / 256, 256>>>(ei);
    scan_kernel<<<1, 1024>>>();
    fill_csr_kernel<<<(EE + 255) / 256, 256>>>(ei);

    const int gemmRows = (NN + 63) / 64;          // 782
    const int combBlocks = (NN * 32 + 255) / 256; // 6250

    // layer 0: x -> h
    gemm_dual_kernel<128, 128><<<dim3(gemmRows, 4), 256>>>(x, w_l0, w_r0);
    combine_kernel<128, true><<<combBlocks, 256>>>(b0, nullptr);
    // layer 1: h -> h
    gemm_dual_kernel<128, 128><<<dim3(gemmRows, 4), 256>>>(nullptr, w_l1, w_r1);
    combine_kernel<128, true><<<combBlocks, 256>>>(b1, nullptr);
    // layer 2: h -> out (64-dim)
    gemm_dual_kernel<128, 64><<<dim3(gemmRows, 2), 256>>>(nullptr, w_l2, w_r2);
    combine_kernel<64, false><<<combBlocks, 256>>>(b2, outp);
}

// round 4
// speedup vs baseline: 1.3060x; 1.3060x over previous
#include <cuda_runtime.h>
#include <cuda_bf16.h>
#include <stdint.h>

#define NN  50000
#define EE  800000
#define NBLK 196            // ceil(NN/256)

// ---------------- scratch (device globals: no allocation allowed) ----------
__device__ __align__(16) float g_t[NN * 128];   // t = h @ w_l
__device__ __align__(16) float g_r[NN * 128];   // r = h @ w_r
__device__ __align__(16) float g_h[NN * 128];   // layer activations
__device__ int   g_degc[NN];
__device__ int   g_rowoff[NN + 1];
__device__ int   g_wptr[NN];
__device__ int   g_csr[EE];
__device__ float g_invdeg[NN];
__device__ int   g_is64;
__device__ int   g_bsum[NBLK];
__device__ int   g_bpre[NBLK];

// ---------------- dtype detection ------------------------------------------
__global__ void detect_kernel(const long long* __restrict__ ei) {
    __shared__ int ok;
    if (threadIdx.x == 0) ok = 1;
    __syncthreads();
    for (int i = threadIdx.x; i < 1024; i += blockDim.x) {
        long long v = ei[i];
        if (v < 0 || v >= NN) ok = 0;
    }
    __syncthreads();
    if (threadIdx.x == 0) g_is64 = ok;
}

__device__ __forceinline__ void load_edge(const void* ei, int e, int is64,
                                          int& s, int& d) {
    if (is64) {
        const long long* p = (const long long*)ei;
        s = (int)p[e];
        d = (int)p[EE + e];
    } else {
        const int* p = (const int*)ei;
        s = p[e];
        d = p[EE + e];
    }
    s = min(max(s, 0), NN - 1);
    d = min(max(d, 0), NN - 1);
}

// ---------------- graph preprocessing --------------------------------------
__global__ void zero_degc_kernel() {
    int i = blockIdx.x * blockDim.x + threadIdx.x;
    if (i < NN) g_degc[i] = 0;
}

__global__ void count_deg_kernel(const void* __restrict__ ei) {
    int e = blockIdx.x * blockDim.x + threadIdx.x;
    if (e < EE) {
        int s, d;
        load_edge(ei, e, g_is64, s, d);
        atomicAdd(&g_degc[d], 1);
    }
}

// phase 1: per-block sum of 256 degree counts
__global__ void blocksum_kernel() {
    int i = blockIdx.x * 256 + threadIdx.x;
    int v = (i < NN) ? g_degc[i] : 0;
#pragma unroll
    for (int off = 16; off > 0; off >>= 1)
        v += __shfl_down_sync(0xffffffffu, v, off);
    __shared__ int ws[8];
    if ((threadIdx.x & 31) == 0) ws[threadIdx.x >> 5] = v;
    __syncthreads();
    if (threadIdx.x == 0) {
        int s = 0;
#pragma unroll
        for (int w = 0; w < 8; w++) s += ws[w];
        g_bsum[blockIdx.x] = s;
    }
}

// phase 2: exclusive scan of NBLK block sums (single small block)
__global__ void scan_bsum_kernel() {
    __shared__ int sh[256];
    int t = threadIdx.x;
    int v = (t < NBLK) ? g_bsum[t] : 0;
    sh[t] = v;
    __syncthreads();
#pragma unroll
    for (int off = 1; off < 256; off <<= 1) {
        int u = (t >= off) ? sh[t - off] : 0;
        __syncthreads();
        sh[t] += u;
        __syncthreads();
    }
    if (t < NBLK) g_bpre[t] = sh[t] - v;   // exclusive
    if (t == NBLK - 1) g_rowoff[NN] = sh[t];
}

// phase 3: intra-block exclusive scan + writeout
__global__ void write_off_kernel() {
    __shared__ int sh[256];
    int t = threadIdx.x;
    int i = blockIdx.x * 256 + t;
    int v = (i < NN) ? g_degc[i] : 0;
    sh[t] = v;
    __syncthreads();
#pragma unroll
    for (int off = 1; off < 256; off <<= 1) {
        int u = (t >= off) ? sh[t - off] : 0;
        __syncthreads();
        sh[t] += u;
        __syncthreads();
    }
    if (i < NN) {
        int excl = g_bpre[blockIdx.x] + sh[t] - v;
        g_rowoff[i] = excl;
        g_wptr[i]   = excl;
        g_invdeg[i] = 1.0f / fmaxf((float)v, 1.0f);
    }
}

__global__ void fill_csr_kernel(const void* __restrict__ ei) {
    int e = blockIdx.x * blockDim.x + threadIdx.x;
    if (e < EE) {
        int s, d;
        load_edge(ei, e, g_is64, s, d);
        int p = atomicAdd(&g_wptr[d], 1);
        if (p >= 0 && p < EE) g_csr[p] = s;
    }
}

// ---------------- dual GEMM: t = A @ Wl, r = A @ Wr ------------------------
// 64x64 block tile, 256 threads, 4x4 microtile, packed fma.rn.f32x2 inner loop.
#define ASTRIDE 66
#define KCH 64

__device__ __forceinline__ unsigned long long pack_dup(float a) {
    unsigned long long r;
    unsigned int u = __float_as_uint(a);
    asm("mov.b64 %0, {%1, %1};" : "=l"(r) : "r"(u));
    return r;
}
__device__ __forceinline__ void ffma2(unsigned long long& d,
                                      unsigned long long a,
                                      unsigned long long b) {
    asm("fma.rn.f32x2 %0, %1, %2, %0;" : "+l"(d) : "l"(a), "l"(b));
}

template <int DINp, int DOUTp>
__global__ __launch_bounds__(256)
void gemm_dual_kernel(const float* __restrict__ A,
                      const float* __restrict__ Wl,
                      const float* __restrict__ Wr) {
    __shared__ __align__(16) float As[KCH * ASTRIDE];
    __shared__ __align__(16) float Ws[KCH * 64];

    const float* Ap = A ? A : g_h;

    const int tid = threadIdx.x;
    const int tx = tid & 15;
    const int ty = tid >> 4;
    const int rowBase = blockIdx.x * 64;
    const int cb = blockIdx.y;
    const bool isL = cb < (DOUTp / 64);
    const float* W = isL ? Wl : Wr;
    const int colBase = (isL ? cb : cb - (DOUTp / 64)) * 64;
    float* Cout = isL ? g_t : g_r;

    unsigned long long accp[4][2];
#pragma unroll
    for (int i = 0; i < 4; i++) { accp[i][0] = 0ull; accp[i][1] = 0ull; }

    for (int kc = 0; kc < DINp; kc += KCH) {
        {
            int row = tid >> 2;
            int kq  = tid & 3;
            int grow = rowBase + row;
#pragma unroll
            for (int p = 0; p < 4; p++) {
                int kk = kq * 4 + p * 16;
                float4 v = make_float4(0.f, 0.f, 0.f, 0.f);
                if (grow < NN)
                    v = *(const float4*)(Ap + (size_t)grow * DINp + kc + kk);
                As[(kk + 0) * ASTRIDE + row] = v.x;
                As[(kk + 1) * ASTRIDE + row] = v.y;
                As[(kk + 2) * ASTRIDE + row] = v.z;
                As[(kk + 3) * ASTRIDE + row] = v.w;
            }
        }
        for (int f = tid; f < KCH * 16; f += 256) {
            int k = f >> 4, c = f & 15;
            float4 v = *(const float4*)(W + (size_t)(kc + k) * DOUTp + colBase + c * 4);
            *(float4*)(Ws + k * 64 + c * 4) = v;
        }
        __syncthreads();

#pragma unroll 8
        for (int k = 0; k < KCH; k++) {
            const float* ap = As + k * ASTRIDE + (ty << 2);
            float2 a0 = *(const float2*)(ap);
            float2 a1 = *(const float2*)(ap + 2);
            ulonglong2 bb = *(const ulonglong2*)(Ws + (k << 6) + (tx << 2));
            unsigned long long A0 = pack_dup(a0.x);
            unsigned long long A1 = pack_dup(a0.y);
            unsigned long long A2 = pack_dup(a1.x);
            unsigned long long A3 = pack_dup(a1.y);
            ffma2(accp[0][0], A0, bb.x); ffma2(accp[0][1], A0, bb.y);
            ffma2(accp[1][0], A1, bb.x); ffma2(accp[1][1], A1, bb.y);
            ffma2(accp[2][0], A2, bb.x); ffma2(accp[2][1], A2, bb.y);
            ffma2(accp[3][0], A3, bb.x); ffma2(accp[3][1], A3, bb.y);
        }
        __syncthreads();
    }

#pragma unroll
    for (int i = 0; i < 4; i++) {
        int grow = rowBase + (ty << 2) + i;
        if (grow < NN) {
            unsigned int c0, c1, c2, c3;
            asm("mov.b64 {%0, %1}, %2;" : "=r"(c0), "=r"(c1) : "l"(accp[i][0]));
            asm("mov.b64 {%0, %1}, %2;" : "=r"(c2), "=r"(c3) : "l"(accp[i][1]));
            float4 o = make_float4(__uint_as_float(c0), __uint_as_float(c1),
                                   __uint_as_float(c2), __uint_as_float(c3));
            *(float4*)(Cout + (size_t)grow * DOUTp + colBase + (tx << 2)) = o;
        }
    }
}

// ---------------- aggregation + combine: out = relu?(mean(t[src]) + b + r) -
template <int D, bool RELU>
__global__ __launch_bounds__(256)
void combine_kernel(const float* __restrict__ bias, float* __restrict__ outp) {
    int gw = (blockIdx.x * blockDim.x + threadIdx.x) >> 5;
    int lane = threadIdx.x & 31;
    if (gw >= NN) return;
    float* out = outp ? outp : g_h;

    int beg = g_rowoff[gw];
    int end = g_rowoff[gw + 1];

    if (D == 128) {
        float4 acc = make_float4(0.f, 0.f, 0.f, 0.f);
        const float* t = g_t;
        int j = beg;
        for (; j + 4 <= end; j += 4) {
            int s0 = g_csr[j], s1 = g_csr[j + 1], s2 = g_csr[j + 2], s3 = g_csr[j + 3];
            float4 v0 = *(const float4*)(t + (size_t)s0 * 128 + lane * 4);
            float4 v1 = *(const float4*)(t + (size_t)s1 * 128 + lane * 4);
            float4 v2 = *(const float4*)(t + (size_t)s2 * 128 + lane * 4);
            float4 v3 = *(const float4*)(t + (size_t)s3 * 128 + lane * 4);
            acc.x += v0.x + v1.x + v2.x + v3.x;
            acc.y += v0.y + v1.y + v2.y + v3.y;
            acc.z += v0.z + v1.z + v2.z + v3.z;
            acc.w += v0.w + v1.w + v2.w + v3.w;
        }
        for (; j < end; j++) {
            int s = g_csr[j];
            float4 v = *(const float4*)(t + (size_t)s * 128 + lane * 4);
            acc.x += v.x; acc.y += v.y; acc.z += v.z; acc.w += v.w;
        }
        float inv = g_invdeg[gw];
        float4 rr = *(const float4*)(g_r + (size_t)gw * 128 + lane * 4);
        float4 o;
        o.x = acc.x * inv + bias[lane * 4 + 0] + rr.x;
        o.y = acc.y * inv + bias[lane * 4 + 1] + rr.y;
        o.z = acc.z * inv + bias[lane * 4 + 2] + rr.z;
        o.w = acc.w * inv + bias[lane * 4 + 3] + rr.w;
        if (RELU) {
            o.x = fmaxf(o.x, 0.f); o.y = fmaxf(o.y, 0.f);
            o.z = fmaxf(o.z, 0.f); o.w = fmaxf(o.w, 0.f);
        }
        *(float4*)(out + (size_t)gw * 128 + lane * 4) = o;
    } else {  // D == 64
        float2 acc = make_float2(0.f, 0.f);
        const float* t = g_t;
        int j = beg;
        for (; j + 4 <= end; j += 4) {
            int s0 = g_csr[j], s1 = g_csr[j + 1], s2 = g_csr[j + 2], s3 = g_csr[j + 3];
            float2 v0 = *(const float2*)(t + (size_t)s0 * 64 + lane * 2);
            float2 v1 = *(const float2*)(t + (size_t)s1 * 64 + lane * 2);
            float2 v2 = *(const float2*)(t + (size_t)s2 * 64 + lane * 2);
            float2 v3 = *(const float2*)(t + (size_t)s3 * 64 + lane * 2);
            acc.x += v0.x + v1.x + v2.x + v3.x;
            acc.y += v0.y + v1.y + v2.y + v3.y;
        }
        for (; j < end; j++) {
            int s = g_csr[j];
            float2 v = *(const float2*)(t + (size_t)s * 64 + lane * 2);
            acc.x += v.x; acc.y += v.y;
        }
        float inv = g_invdeg[gw];
        float2 rr = *(const float2*)(g_r + (size_t)gw * 64 + lane * 2);
        float2 o;
        o.x = acc.x * inv + bias[lane * 2 + 0] + rr.x;
        o.y = acc.y * inv + bias[lane * 2 + 1] + rr.y;
        if (RELU) { o.x = fmaxf(o.x, 0.f); o.y = fmaxf(o.y, 0.f); }
        *(float2*)(out + (size_t)gw * 64 + lane * 2) = o;
    }
}

// ---------------- launch ----------------------------------------------------
extern "C" void kernel_launch(void* const* d_in, const int* in_sizes, int n_in,
                              void* d_out, int out_size) {
    const float* x    = (const float*)d_in[0];
    const void*  ei   = d_in[1];
    const float* w_l0 = (const float*)d_in[2];
    const float* b0   = (const float*)d_in[3];
    const float* w_r0 = (const float*)d_in[4];
    const float* w_l1 = (const float*)d_in[5];
    const float* b1   = (const float*)d_in[6];
    const float* w_r1 = (const float*)d_in[7];
    const float* w_l2 = (const float*)d_in[8];
    const float* b2   = (const float*)d_in[9];
    const float* w_r2 = (const float*)d_in[10];
    float* outp = (float*)d_out;

    // graph preprocessing
    detect_kernel<<<1, 256>>>((const long long*)ei);
    zero_degc_kernel<<<NBLK, 256>>>();
    count_deg_kernel<<<(EE + 255) / 256, 256>>>(ei);
    blocksum_kernel<<<NBLK, 256>>>();
    scan_bsum_kernel<<<1, 256>>>();
    write_off_kernel<<<NBLK, 256>>>();
    fill_csr_kernel<<<(EE + 255) / 256, 256>>>(ei);

    const int gemmRows = (NN + 63) / 64;          // 782
    const int combBlocks = (NN * 32 + 255) / 256; // 6250

    // layer 0: x -> h
    gemm_dual_kernel<128, 128><<<dim3(gemmRows, 4), 256>>>(x, w_l0, w_r0);
    combine_kernel<128, true><<<combBlocks, 256>>>(b0, nullptr);
    // layer 1: h -> h
    gemm_dual_kernel<128, 128><<<dim3(gemmRows, 4), 256>>>(nullptr, w_l1, w_r1);
    combine_kernel<128, true><<<combBlocks, 256>>>(b1, nullptr);
    // layer 2: h -> out (64-dim)
    gemm_dual_kernel<128, 64><<<dim3(gemmRows, 2), 256>>>(nullptr, w_l2, w_r2);
    combine_kernel<64, false><<<combBlocks, 256>>>(b2, outp);
}

// round 5
// speedup vs baseline: 1.3066x; 1.0004x over previous
#include <cuda_runtime.h>
#include <cuda_bf16.h>
#include <stdint.h>

#define NN  50000
#define EE  800000
#define NBLK 196            // ceil(NN/256)

// ---------------- scratch (device globals: zero-initialized at load) -------
__device__ __align__(16) float g_t[NN * 128];   // t = h @ w_l
__device__ __align__(16) float g_r[NN * 128];   // r = h @ w_r
__device__ __align__(16) float g_h[NN * 128];   // layer activations
__device__ int   g_degc[NN];                    // zero at load; re-zeroed each launch
__device__ int   g_rowoff[NN + 1];
__device__ int   g_wptr[NN];
__device__ int   g_csr[EE];
__device__ float g_invdeg[NN];
__device__ int   g_bsum[NBLK];
__device__ int   g_bpre[NBLK];

// ---------------- inline dtype probe (warp-collective, deterministic) ------
// Reads the first 32 entries as int64: genuine int64 indices are all in
// [0, NN); int32 data read as int64 fuses random pairs -> out of range.
__device__ __forceinline__ int probe_is64(const void* ei) {
    int lane = threadIdx.x & 31;
    long long v = ((const long long*)ei)[lane];
    unsigned ok = __ballot_sync(0xffffffffu, v >= 0 && v < NN);
    return ok == 0xffffffffu;
}

__device__ __forceinline__ void load_edge(const void* ei, int e, int is64,
                                          int& s, int& d) {
    if (is64) {
        const long long* p = (const long long*)ei;
        s = (int)p[e];
        d = (int)p[EE + e];
    } else {
        const int* p = (const int*)ei;
        s = p[e];
        d = p[EE + e];
    }
    s = min(max(s, 0), NN - 1);
    d = min(max(d, 0), NN - 1);
}

// ---------------- graph preprocessing --------------------------------------
__global__ void count_deg_kernel(const void* __restrict__ ei) {
    int is64 = probe_is64(ei);
    int e = blockIdx.x * blockDim.x + threadIdx.x;
    if (e < EE) {
        int s, d;
        load_edge(ei, e, is64, s, d);
        atomicAdd(&g_degc[d], 1);
    }
}

__global__ void blocksum_kernel() {
    int i = blockIdx.x * 256 + threadIdx.x;
    int v = (i < NN) ? g_degc[i] : 0;
#pragma unroll
    for (int off = 16; off > 0; off >>= 1)
        v += __shfl_down_sync(0xffffffffu, v, off);
    __shared__ int ws[8];
    if ((threadIdx.x & 31) == 0) ws[threadIdx.x >> 5] = v;
    __syncthreads();
    if (threadIdx.x == 0) {
        int s = 0;
#pragma unroll
        for (int w = 0; w < 8; w++) s += ws[w];
        g_bsum[blockIdx.x] = s;
    }
}

__global__ void scan_bsum_kernel() {
    __shared__ int sh[256];
    int t = threadIdx.x;
    int v = (t < NBLK) ? g_bsum[t] : 0;
    sh[t] = v;
    __syncthreads();
#pragma unroll
    for (int off = 1; off < 256; off <<= 1) {
        int u = (t >= off) ? sh[t - off] : 0;
        __syncthreads();
        sh[t] += u;
        __syncthreads();
    }
    if (t < NBLK) g_bpre[t] = sh[t] - v;
    if (t == NBLK - 1) g_rowoff[NN] = sh[t];
}

// intra-block exclusive scan + writeout; re-zeros g_degc for the next launch
__global__ void write_off_kernel() {
    __shared__ int sh[256];
    int t = threadIdx.x;
    int i = blockIdx.x * 256 + t;
    int v = (i < NN) ? g_degc[i] : 0;
    sh[t] = v;
    __syncthreads();
#pragma unroll
    for (int off = 1; off < 256; off <<= 1) {
        int u = (t >= off) ? sh[t - off] : 0;
        __syncthreads();
        sh[t] += u;
        __syncthreads();
    }
    if (i < NN) {
        int excl = g_bpre[blockIdx.x] + sh[t] - v;
        g_rowoff[i] = excl;
        g_wptr[i]   = excl;
        g_invdeg[i] = 1.0f / fmaxf((float)v, 1.0f);
        g_degc[i]   = 0;   // invariant restored for next launch/replay
    }
}

__global__ void fill_csr_kernel(const void* __restrict__ ei) {
    int is64 = probe_is64(ei);
    int e = blockIdx.x * blockDim.x + threadIdx.x;
    if (e < EE) {
        int s, d;
        load_edge(ei, e, is64, s, d);
        int p = atomicAdd(&g_wptr[d], 1);
        if (p >= 0 && p < EE) g_csr[p] = s;
    }
}

// ---------------- dual GEMM: t = A @ Wl, r = A @ Wr ------------------------
// 128x(COLT) block tile, 256 threads, 8x(COLT/16) microtile, fma.rn.f32x2.
// blockIdx.y: 0 -> t = A@Wl, 1 -> r = A@Wr. K=128 in 4 chunks of 32.
#define AST 132
#define KC2 32

__device__ __forceinline__ unsigned long long pack_dup(float a) {
    unsigned long long r;
    unsigned int u = __float_as_uint(a);
    asm("mov.b64 %0, {%1, %1};" : "=l"(r) : "r"(u));
    return r;
}
__device__ __forceinline__ void ffma2(unsigned long long& d,
                                      unsigned long long a,
                                      unsigned long long b) {
    asm("fma.rn.f32x2 %0, %1, %2, %0;" : "+l"(d) : "l"(a), "l"(b));
}
__device__ __forceinline__ float2 unpack2(unsigned long long v) {
    unsigned int lo, hi;
    asm("mov.b64 {%0, %1}, %2;" : "=r"(lo), "=r"(hi) : "l"(v));
    return make_float2(__uint_as_float(lo), __uint_as_float(hi));
}

template <int COLT>   // 128 (hidden layers) or 64 (output layer)
__global__ __launch_bounds__(256)
void gemm_dual_kernel(const float* __restrict__ A,
                      const float* __restrict__ Wl,
                      const float* __restrict__ Wr) {
    constexpr int DIN = 128;
    constexpr int CPT = COLT / 16;    // cols per thread: 8 or 4
    constexpr int NPAIR = CPT / 2;    // f32x2 pairs: 4 or 2

    __shared__ __align__(16) float As[KC2 * AST];    // 16.9 KB
    __shared__ __align__(16) float Ws[KC2 * COLT];   // 16 / 8 KB

    const float* Ap = A ? A : g_h;
    const int tid = threadIdx.x;
    const int tx = tid & 15;
    const int ty = tid >> 4;
    const int rowBase = blockIdx.x * 128;
    const bool isL = (blockIdx.y == 0);
    const float* W = isL ? Wl : Wr;
    float* Cout = isL ? g_t : g_r;

    unsigned long long acc[8][NPAIR];
#pragma unroll
    for (int i = 0; i < 8; i++)
#pragma unroll
        for (int j = 0; j < NPAIR; j++) acc[i][j] = 0ull;

    const int arow = tid >> 1;            // 0..127
    const int ahalf = (tid & 1) * 16;     // 0 or 16

    for (int kc = 0; kc < DIN; kc += KC2) {
        // stage A chunk transposed: As[k][row], 128 rows x 32 k
        {
            int grow = rowBase + arow;
            const float* src = Ap + (size_t)grow * DIN + kc + ahalf;
#pragma unroll
            for (int q = 0; q < 4; q++) {
                float4 v = make_float4(0.f, 0.f, 0.f, 0.f);
                if (grow < NN) v = *(const float4*)(src + q * 4);
                int kk = ahalf + q * 4;
                As[(kk + 0) * AST + arow] = v.x;
                As[(kk + 1) * AST + arow] = v.y;
                As[(kk + 2) * AST + arow] = v.z;
                As[(kk + 3) * AST + arow] = v.w;
            }
        }
        // stage W chunk: 32 k x COLT cols
#pragma unroll
        for (int f = tid; f < KC2 * (COLT / 4); f += 256) {
            int k = f / (COLT / 4), c = f % (COLT / 4);
            *(float4*)(Ws + k * COLT + c * 4) =
                *(const float4*)(W + (size_t)(kc + k) * COLT + c * 4);
        }
        __syncthreads();

#pragma unroll 8
        for (int k = 0; k < KC2; k++) {
            const float* ap = As + k * AST + (ty << 3);
            float4 a0 = *(const float4*)ap;
            float4 a1 = *(const float4*)(ap + 4);
            const unsigned long long* bp =
                (const unsigned long long*)(Ws + k * COLT + tx * CPT);
            unsigned long long b[NPAIR];
#pragma unroll
            for (int j = 0; j < NPAIR; j++) b[j] = bp[j];
            float ar[8] = {a0.x, a0.y, a0.z, a0.w, a1.x, a1.y, a1.z, a1.w};
#pragma unroll
            for (int i = 0; i < 8; i++) {
                unsigned long long ad = pack_dup(ar[i]);
#pragma unroll
                for (int j = 0; j < NPAIR; j++) ffma2(acc[i][j], ad, b[j]);
            }
        }
        __syncthreads();
    }

#pragma unroll
    for (int i = 0; i < 8; i++) {
        int grow = rowBase + (ty << 3) + i;
        if (grow < NN) {
            float* dst = Cout + (size_t)grow * COLT + tx * CPT;
#pragma unroll
            for (int j = 0; j < NPAIR; j += 2) {
                float2 p0 = unpack2(acc[i][j]);
                float2 p1 = unpack2(acc[i][j + 1]);
                *(float4*)(dst + j * 2) = make_float4(p0.x, p0.y, p1.x, p1.y);
            }
        }
    }
}

// ---------------- aggregation + combine: out = relu?(mean(t[src]) + b + r) -
template <int D, bool RELU>
__global__ __launch_bounds__(256)
void combine_kernel(const float* __restrict__ bias, float* __restrict__ outp) {
    int gw = (blockIdx.x * blockDim.x + threadIdx.x) >> 5;
    int lane = threadIdx.x & 31;
    if (gw >= NN) return;
    float* out = outp ? outp : g_h;

    int beg = g_rowoff[gw];
    int end = g_rowoff[gw + 1];

    if (D == 128) {
        float4 acc = make_float4(0.f, 0.f, 0.f, 0.f);
        const float* t = g_t;
        int j = beg;
        for (; j + 4 <= end; j += 4) {
            int s0 = g_csr[j], s1 = g_csr[j + 1], s2 = g_csr[j + 2], s3 = g_csr[j + 3];
            float4 v0 = *(const float4*)(t + (size_t)s0 * 128 + lane * 4);
            float4 v1 = *(const float4*)(t + (size_t)s1 * 128 + lane * 4);
            float4 v2 = *(const float4*)(t + (size_t)s2 * 128 + lane * 4);
            float4 v3 = *(const float4*)(t + (size_t)s3 * 128 + lane * 4);
            acc.x += v0.x + v1.x + v2.x + v3.x;
            acc.y += v0.y + v1.y + v2.y + v3.y;
            acc.z += v0.z + v1.z + v2.z + v3.z;
            acc.w += v0.w + v1.w + v2.w + v3.w;
        }
        for (; j < end; j++) {
            int s = g_csr[j];
            float4 v = *(const float4*)(t + (size_t)s * 128 + lane * 4);
            acc.x += v.x; acc.y += v.y; acc.z += v.z; acc.w += v.w;
        }
        float inv = g_invdeg[gw];
        float4 rr = *(const float4*)(g_r + (size_t)gw * 128 + lane * 4);
        float4 o;
        o.x = acc.x * inv + bias[lane * 4 + 0] + rr.x;
        o.y = acc.y * inv + bias[lane * 4 + 1] + rr.y;
        o.z = acc.z * inv + bias[lane * 4 + 2] + rr.z;
        o.w = acc.w * inv + bias[lane * 4 + 3] + rr.w;
        if (RELU) {
            o.x = fmaxf(o.x, 0.f); o.y = fmaxf(o.y, 0.f);
            o.z = fmaxf(o.z, 0.f); o.w = fmaxf(o.w, 0.f);
        }
        *(float4*)(out + (size_t)gw * 128 + lane * 4) = o;
    } else {  // D == 64
        float2 acc = make_float2(0.f, 0.f);
        const float* t = g_t;
        int j = beg;
        for (; j + 4 <= end; j += 4) {
            int s0 = g_csr[j], s1 = g_csr[j + 1], s2 = g_csr[j + 2], s3 = g_csr[j + 3];
            float2 v0 = *(const float2*)(t + (size_t)s0 * 64 + lane * 2);
            float2 v1 = *(const float2*)(t + (size_t)s1 * 64 + lane * 2);
            float2 v2 = *(const float2*)(t + (size_t)s2 * 64 + lane * 2);
            float2 v3 = *(const float2*)(t + (size_t)s3 * 64 + lane * 2);
            acc.x += v0.x + v1.x + v2.x + v3.x;
            acc.y += v0.y + v1.y + v2.y + v3.y;
        }
        for (; j < end; j++) {
            int s = g_csr[j];
            float2 v = *(const float2*)(t + (size_t)s * 64 + lane * 2);
            acc.x += v.x; acc.y += v.y;
        }
        float inv = g_invdeg[gw];
        float2 rr = *(const float2*)(g_r + (size_t)gw * 64 + lane * 2);
        float2 o;
        o.x = acc.x * inv + bias[lane * 2 + 0] + rr.x;
        o.y = acc.y * inv + bias[lane * 2 + 1] + rr.y;
        if (RELU) { o.x = fmaxf(o.x, 0.f); o.y = fmaxf(o.y, 0.f); }
        *(float2*)(out + (size_t)gw * 64 + lane * 2) = o;
    }
}

// ---------------- launch ----------------------------------------------------
extern "C" void kernel_launch(void* const* d_in, const int* in_sizes, int n_in,
                              void* d_out, int out_size) {
    const float* x    = (const float*)d_in[0];
    const void*  ei   = d_in[1];
    const float* w_l0 = (const float*)d_in[2];
    const float* b0   = (const float*)d_in[3];
    const float* w_r0 = (const float*)d_in[4];
    const float* w_l1 = (const float*)d_in[5];
    const float* b1   = (const float*)d_in[6];
    const float* w_r1 = (const float*)d_in[7];
    const float* w_l2 = (const float*)d_in[8];
    const float* b2   = (const float*)d_in[9];
    const float* w_r2 = (const float*)d_in[10];
    float* outp = (float*)d_out;

    // graph preprocessing (5 launches)
    count_deg_kernel<<<(EE + 255) / 256, 256>>>(ei);
    blocksum_kernel<<<NBLK, 256>>>();
    scan_bsum_kernel<<<1, 256>>>();
    write_off_kernel<<<NBLK, 256>>>();
    fill_csr_kernel<<<(EE + 255) / 256, 256>>>(ei);

    const int gemmRows = (NN + 127) / 128;        // 391
    const int combBlocks = (NN * 32 + 255) / 256; // 6250

    // layer 0: x -> h
    gemm_dual_kernel<128><<<dim3(gemmRows, 2), 256>>>(x, w_l0, w_r0);
    combine_kernel<128, true><<<combBlocks, 256>>>(b0, nullptr);
    // layer 1: h -> h
    gemm_dual_kernel<128><<<dim3(gemmRows, 2), 256>>>(nullptr, w_l1, w_r1);
    combine_kernel<128, true><<<combBlocks, 256>>>(b1, nullptr);
    // layer 2: h -> out (64-dim)
    gemm_dual_kernel<64><<<dim3(gemmRows, 2), 256>>>(nullptr, w_l2, w_r2);
    combine_kernel<64, false><<<combBlocks, 256>>>(b2, outp);
}

// round 7
// speedup vs baseline: 1.7351x; 1.3280x over previous
#include <cuda_runtime.h>
#include <cuda_bf16.h>
#include <mma.h>
#include <stdint.h>

using namespace nvcuda;

#define NN  50000
#define EE  800000
#define NBLK 196            // ceil(NN/256)
#define NPAD (NN + 128)     // row padding so wmma stores in the last CTA stay in-bounds

// ---------------- scratch (device globals) ----------------------------------
__device__ __align__(16) float g_t[NPAD * 128];
__device__ __align__(16) float g_r[NPAD * 128];
__device__ __align__(16) float g_h[NPAD * 128];
__device__ int   g_degc[NN];
__device__ int   g_rowoff[NN + 1];
__device__ int   g_wptr[NN];
__device__ int   g_csr[EE];
__device__ float g_invdeg[NN];
__device__ int   g_bsum[NBLK];
__device__ int   g_bpre[NBLK];

// ---------------- edge dtype probe ------------------------------------------
__device__ __forceinline__ int probe_is64(const void* ei) {
    int lane = threadIdx.x & 31;
    long long v = ((const long long*)ei)[lane];
    unsigned ok = __ballot_sync(0xffffffffu, v >= 0 && v < NN);
    return ok == 0xffffffffu;
}

__device__ __forceinline__ void load_edge(const void* ei, int e, int is64,
                                          int& s, int& d) {
    if (is64) {
        const long long* p = (const long long*)ei;
        s = (int)p[e];
        d = (int)p[EE + e];
    } else {
        const int* p = (const int*)ei;
        s = p[e];
        d = p[EE + e];
    }
    s = min(max(s, 0), NN - 1);
    d = min(max(d, 0), NN - 1);
}

// ---------------- graph preprocessing ---------------------------------------
__global__ void count_deg_kernel(const void* __restrict__ ei) {
    int is64 = probe_is64(ei);
    int e = blockIdx.x * blockDim.x + threadIdx.x;
    if (e < EE) {
        int s, d;
        load_edge(ei, e, is64, s, d);
        atomicAdd(&g_degc[d], 1);
    }
}

__global__ void blocksum_kernel() {
    int i = blockIdx.x * 256 + threadIdx.x;
    int v = (i < NN) ? g_degc[i] : 0;
#pragma unroll
    for (int off = 16; off > 0; off >>= 1)
        v += __shfl_down_sync(0xffffffffu, v, off);
    __shared__ int ws[8];
    if ((threadIdx.x & 31) == 0) ws[threadIdx.x >> 5] = v;
    __syncthreads();
    if (threadIdx.x == 0) {
        int s = 0;
#pragma unroll
        for (int w = 0; w < 8; w++) s += ws[w];
        g_bsum[blockIdx.x] = s;
    }
}

__global__ void scan_bsum_kernel() {
    __shared__ int sh[256];
    int t = threadIdx.x;
    int v = (t < NBLK) ? g_bsum[t] : 0;
    sh[t] = v;
    __syncthreads();
#pragma unroll
    for (int off = 1; off < 256; off <<= 1) {
        int u = (t >= off) ? sh[t - off] : 0;
        __syncthreads();
        sh[t] += u;
        __syncthreads();
    }
    if (t < NBLK) g_bpre[t] = sh[t] - v;
    if (t == NBLK - 1) g_rowoff[NN] = sh[t];
}

__global__ void write_off_kernel() {
    __shared__ int sh[256];
    int t = threadIdx.x;
    int i = blockIdx.x * 256 + t;
    int v = (i < NN) ? g_degc[i] : 0;
    sh[t] = v;
    __syncthreads();
#pragma unroll
    for (int off = 1; off < 256; off <<= 1) {
        int u = (t >= off) ? sh[t - off] : 0;
        __syncthreads();
        sh[t] += u;
        __syncthreads();
    }
    if (i < NN) {
        int excl = g_bpre[blockIdx.x] + sh[t] - v;
        g_rowoff[i] = excl;
        g_wptr[i]   = excl;
        g_invdeg[i] = 1.0f / fmaxf((float)v, 1.0f);
        g_degc[i]   = 0;
    }
}

__global__ void fill_csr_kernel(const void* __restrict__ ei) {
    int is64 = probe_is64(ei);
    int e = blockIdx.x * blockDim.x + threadIdx.x;
    if (e < EE) {
        int s, d;
        load_edge(ei, e, is64, s, d);
        int p = atomicAdd(&g_wptr[d], 1);
        if (p >= 0 && p < EE) g_csr[p] = s;
    }
}

// ---------------- wmma bf16 split GEMM: t = A @ Wl, r = A @ Wr --------------
// fp32 -> (hi, lo) bf16 split; C = Ahi*Whi + Ahi*Wlo + Alo*Whi in fp32 acc.
// CTA: 128 rows x COLT cols; blockIdx.y selects Wl->g_t / Wr->g_r.
// 8 warps in 4(m) x 2(n) grid; warp tile 32m x (COLT/2)n.
#define KP 40      // A smem row stride (elems), mult of 8, breaks 32-bank repeat

template <int COLT>   // 128 or 64
__global__ __launch_bounds__(256)
void gemm_wmma_kernel(const float* __restrict__ A,
                      const float* __restrict__ Wl,
                      const float* __restrict__ Wr) {
    constexpr int CP = COLT + 8;
    constexpr int NF = COLT / 32;     // 16-col frags per warp (4 or 2)

    __shared__ __align__(32) __nv_bfloat16 Ahi[128 * KP];
    __shared__ __align__(32) __nv_bfloat16 Alo[128 * KP];
    __shared__ __align__(32) __nv_bfloat16 Whi[32 * CP];
    __shared__ __align__(32) __nv_bfloat16 Wlo[32 * CP];

    const float* Ap = A ? A : g_h;
    const float* W  = blockIdx.y ? Wr : Wl;
    float* Cout     = blockIdx.y ? g_r : g_t;

    const int tid = threadIdx.x;
    const int wid = tid >> 5;
    const int wm = wid & 3;           // m-tile 0..3
    const int wn = wid >> 2;          // n-half 0..1
    const int rowBase = blockIdx.x * 128;

    wmma::fragment<wmma::accumulator, 16, 16, 16, float> acc[2][NF];
#pragma unroll
    for (int m = 0; m < 2; m++)
#pragma unroll
        for (int f = 0; f < NF; f++) wmma::fill_fragment(acc[m][f], 0.0f);

    const int arow = tid >> 1;            // 0..127
    const int ahalf = (tid & 1) * 16;     // 0 or 16

    for (int kc = 0; kc < 128; kc += 32) {
        // ---- stage A chunk: 128 rows x 32 k, fp32 -> hi/lo bf16 ----
        {
            int grow = rowBase + arow;
            const float* src = Ap + (size_t)grow * 128 + kc + ahalf;
            __nv_bfloat16* dh = Ahi + arow * KP + ahalf;
            __nv_bfloat16* dl = Alo + arow * KP + ahalf;
#pragma unroll
            for (int q = 0; q < 4; q++) {
                float4 v = make_float4(0.f, 0.f, 0.f, 0.f);
                if (grow < NN) v = *(const float4*)(src + q * 4);
                float vs[4] = {v.x, v.y, v.z, v.w};
#pragma unroll
                for (int e = 0; e < 4; e++) {
                    __nv_bfloat16 h = __float2bfloat16(vs[e]);
                    __nv_bfloat16 l = __float2bfloat16(vs[e] - __bfloat162float(h));
                    dh[q * 4 + e] = h;
                    dl[q * 4 + e] = l;
                }
            }
        }
        // ---- stage W chunk: 32 k x COLT n ----
#pragma unroll
        for (int f = tid; f < 32 * COLT; f += 256) {
            int k = f / COLT, n = f % COLT;
            float w = W[(size_t)(kc + k) * COLT + n];
            __nv_bfloat16 h = __float2bfloat16(w);
            __nv_bfloat16 l = __float2bfloat16(w - __bfloat162float(h));
            Whi[k * CP + n] = h;
            Wlo[k * CP + n] = l;
        }
        __syncthreads();

#pragma unroll
        for (int kk = 0; kk < 32; kk += 16) {
            wmma::fragment<wmma::matrix_a, 16, 16, 16, __nv_bfloat16,
                           wmma::row_major> ah0, ah1, al0, al1;
            wmma::load_matrix_sync(ah0, Ahi + (wm * 32) * KP + kk, KP);
            wmma::load_matrix_sync(ah1, Ahi + (wm * 32 + 16) * KP + kk, KP);
            wmma::load_matrix_sync(al0, Alo + (wm * 32) * KP + kk, KP);
            wmma::load_matrix_sync(al1, Alo + (wm * 32 + 16) * KP + kk, KP);
#pragma unroll
            for (int f = 0; f < NF; f++) {
                wmma::fragment<wmma::matrix_b, 16, 16, 16, __nv_bfloat16,
                               wmma::row_major> bh, bl;
                int ncol = wn * (COLT / 2) + f * 16;
                wmma::load_matrix_sync(bh, Whi + kk * CP + ncol, CP);
                wmma::load_matrix_sync(bl, Wlo + kk * CP + ncol, CP);
                wmma::mma_sync(acc[0][f], ah0, bh, acc[0][f]);
                wmma::mma_sync(acc[1][f], ah1, bh, acc[1][f]);
                wmma::mma_sync(acc[0][f], ah0, bl, acc[0][f]);
                wmma::mma_sync(acc[1][f], ah1, bl, acc[1][f]);
                wmma::mma_sync(acc[0][f], al0, bh, acc[0][f]);
                wmma::mma_sync(acc[1][f], al1, bh, acc[1][f]);
            }
        }
        __syncthreads();
    }

    // ---- epilogue: direct wmma store (Cout padded to NPAD rows) ----
#pragma unroll
    for (int m = 0; m < 2; m++) {
        int r = rowBase + wm * 32 + m * 16;
#pragma unroll
        for (int f = 0; f < NF; f++) {
            int c = wn * (COLT / 2) + f * 16;
            wmma::store_matrix_sync(Cout + (size_t)r * COLT + c, acc[m][f],
                                    COLT, wmma::mem_row_major);
        }
    }
}

// ---------------- aggregation + combine -------------------------------------
template <int D, bool RELU>
__global__ __launch_bounds__(256)
void combine_kernel(const float* __restrict__ bias, float* __restrict__ outp) {
    int gw = (blockIdx.x * blockDim.x + threadIdx.x) >> 5;
    int lane = threadIdx.x & 31;
    if (gw >= NN) return;
    float* out = outp ? outp : g_h;

    int beg = g_rowoff[gw];
    int end = g_rowoff[gw + 1];

    if (D == 128) {
        float4 acc = make_float4(0.f, 0.f, 0.f, 0.f);
        const float* t = g_t;
        int j = beg;
        for (; j + 4 <= end; j += 4) {
            int s0 = g_csr[j], s1 = g_csr[j + 1], s2 = g_csr[j + 2], s3 = g_csr[j + 3];
            float4 v0 = *(const float4*)(t + (size_t)s0 * 128 + lane * 4);
            float4 v1 = *(const float4*)(t + (size_t)s1 * 128 + lane * 4);
            float4 v2 = *(const float4*)(t + (size_t)s2 * 128 + lane * 4);
            float4 v3 = *(const float4*)(t + (size_t)s3 * 128 + lane * 4);
            acc.x += v0.x + v1.x + v2.x + v3.x;
            acc.y += v0.y + v1.y + v2.y + v3.y;
            acc.z += v0.z + v1.z + v2.z + v3.z;
            acc.w += v0.w + v1.w + v2.w + v3.w;
        }
        for (; j < end; j++) {
            int s = g_csr[j];
            float4 v = *(const float4*)(t + (size_t)s * 128 + lane * 4);
            acc.x += v.x; acc.y += v.y; acc.z += v.z; acc.w += v.w;
        }
        float inv = g_invdeg[gw];
        float4 rr = *(const float4*)(g_r + (size_t)gw * 128 + lane * 4);
        float4 o;
        o.x = acc.x * inv + bias[lane * 4 + 0] + rr.x;
        o.y = acc.y * inv + bias[lane * 4 + 1] + rr.y;
        o.z = acc.z * inv + bias[lane * 4 + 2] + rr.z;
        o.w = acc.w * inv + bias[lane * 4 + 3] + rr.w;
        if (RELU) {
            o.x = fmaxf(o.x, 0.f); o.y = fmaxf(o.y, 0.f);
            o.z = fmaxf(o.z, 0.f); o.w = fmaxf(o.w, 0.f);
        }
        *(float4*)(out + (size_t)gw * 128 + lane * 4) = o;
    } else {
        float2 acc = make_float2(0.f, 0.f);
        const float* t = g_t;
        int j = beg;
        for (; j + 4 <= end; j += 4) {
            int s0 = g_csr[j], s1 = g_csr[j + 1], s2 = g_csr[j + 2], s3 = g_csr[j + 3];
            float2 v0 = *(const float2*)(t + (size_t)s0 * 64 + lane * 2);
            float2 v1 = *(const float2*)(t + (size_t)s1 * 64 + lane * 2);
            float2 v2 = *(const float2*)(t + (size_t)s2 * 64 + lane * 2);
            float2 v3 = *(const float2*)(t + (size_t)s3 * 64 + lane * 2);
            acc.x += v0.x + v1.x + v2.x + v3.x;
            acc.y += v0.y + v1.y + v2.y + v3.y;
        }
        for (; j < end; j++) {
            int s = g_csr[j];
            float2 v = *(const float2*)(t + (size_t)s * 64 + lane * 2);
            acc.x += v.x; acc.y += v.y;
        }
        float inv = g_invdeg[gw];
        float2 rr = *(const float2*)(g_r + (size_t)gw * 64 + lane * 2);
        float2 o;
        o.x = acc.x * inv + bias[lane * 2 + 0] + rr.x;
        o.y = acc.y * inv + bias[lane * 2 + 1] + rr.y;
        if (RELU) { o.x = fmaxf(o.x, 0.f); o.y = fmaxf(o.y, 0.f); }
        *(float2*)(out + (size_t)gw * 64 + lane * 2) = o;
    }
}

// ---------------- launch ------------------------------------------------------
extern "C" void kernel_launch(void* const* d_in, const int* in_sizes, int n_in,
                              void* d_out, int out_size) {
    const float* x    = (const float*)d_in[0];
    const void*  ei   = d_in[1];
    const float* w_l0 = (const float*)d_in[2];
    const float* b0   = (const float*)d_in[3];
    const float* w_r0 = (const float*)d_in[4];
    const float* w_l1 = (const float*)d_in[5];
    const float* b1   = (const float*)d_in[6];
    const float* w_r1 = (const float*)d_in[7];
    const float* w_l2 = (const float*)d_in[8];
    const float* b2   = (const float*)d_in[9];
    const float* w_r2 = (const float*)d_in[10];
    float* outp = (float*)d_out;

    const int gemmBlocks = (NN + 127) / 128;      // 391
    const int combBlocks = (NN * 32 + 255) / 256; // 6250

    count_deg_kernel<<<(EE + 255) / 256, 256>>>(ei);
    blocksum_kernel<<<NBLK, 256>>>();
    scan_bsum_kernel<<<1, 256>>>();
    gemm_wmma_kernel<128><<<dim3(gemmBlocks, 2), 256>>>(x, w_l0, w_r0);
    write_off_kernel<<<NBLK, 256>>>();
    fill_csr_kernel<<<(EE + 255) / 256, 256>>>(ei);
    combine_kernel<128, true><<<combBlocks, 256>>>(b0, nullptr);
    gemm_wmma_kernel<128><<<dim3(gemmBlocks, 2), 256>>>(nullptr, w_l1, w_r1);
    combine_kernel<128, true><<<combBlocks, 256>>>(b1, nullptr);
    gemm_wmma_kernel<64><<<dim3(gemmBlocks, 2), 256>>>(nullptr, w_l2, w_r2);
    combine_kernel<64, false><<<combBlocks, 256>>>(b2, outp);
}